// round 5
// baseline (speedup 1.0000x reference)
#include <cuda_runtime.h>

// Problem constants: B=8, C=512, H=W=64
#define CK 512
#define BB 8
#define HW 4096   // 64*64

// Scratch (device globals: allocation-free rule)
__device__ float g_Wt[2 * CK * CK];                 // transposed weights [br][c][o]
__device__ float g_F[2ull * BB * CK * HW];          // f per branch  (128 MB)
__device__ float g_S[2ull * BB * CK * HW];          // S per branch  (128 MB)
__device__ float g_mx[2 * BB * HW];                 // softmax max per (br,b,i,j)
__device__ float g_sm[2 * BB * HW];                 // softmax sumexp

// ---- packed f32x2 FMA (SASS FFMA2; only reachable via PTX) ----
__device__ __forceinline__ void ffma2(unsigned long long& d,
                                      unsigned long long a,
                                      unsigned long long b) {
    asm("fma.rn.f32x2 %0, %1, %2, %3;" : "=l"(d) : "l"(a), "l"(b), "l"(d));
}
__device__ __forceinline__ float2 unpk(unsigned long long v) {
    float2 r;
    asm("mov.b64 {%0, %1}, %2;" : "=f"(r.x), "=f"(r.y) : "l"(v));
    return r;
}

// ============================================================
// K0: transpose W[o][c] -> Wt[c][o] for coalesced GEMM A loads
// ============================================================
__global__ __launch_bounds__(256) void k0_transpose(const float* __restrict__ Wo,
                                                    const float* __restrict__ Ws) {
    int idx = blockIdx.x * 256 + threadIdx.x;     // 0 .. 2*512*512-1
    int br  = idx >> 18;
    int r   = idx & 262143;
    int o   = r >> 9;
    int c   = r & 511;
    const float* W = br ? Ws : Wo;
    g_Wt[br * 262144 + c * 512 + o] = W[o * 512 + c];
}

// ============================================================
// K1: f[br,b] (512x4096) = W[br] (512x512) @ x[br,b] (512x4096)
//     128x128x16 tile, 256 threads, 8x8 per thread, FFMA2.
//     A tile stored DUPLICATED in smem so one LDS.64 gives (a,a).
// ============================================================
__global__ __launch_bounds__(256, 2) void k1_gemm(const float* __restrict__ opt,
                                                  const float* __restrict__ sar) {
    __shared__ float Asd[16][256];   // duplicated A tile: Asd[k][2m..2m+1] = W[m0+m][k0+k]
    __shared__ float Bs[16][128];    // Bs[k][n] = x[k0+k][n0+n]

    int br = blockIdx.z >> 3, b = blockIdx.z & 7;
    const float* X  = (br ? sar : opt) + (size_t)b * CK * HW;
    const float* Wt = g_Wt + br * CK * CK;
    int m0 = blockIdx.y * 128;
    int n0 = blockIdx.x * 128;
    int tm = threadIdx.x >> 4;       // 0..15
    int tn = threadIdx.x & 15;       // 0..15

    unsigned long long acc[8][4];
#pragma unroll
    for (int i = 0; i < 8; i++)
#pragma unroll
        for (int q = 0; q < 4; q++) acc[i][q] = 0ull;

    for (int k0 = 0; k0 < CK; k0 += 16) {
        // ---- stage tiles ----
#pragma unroll
        for (int r = 0; r < 2; r++) {
            int linear = threadIdx.x + r * 256;  // 0..511
            int k   = linear >> 5;               // 0..15
            int q32 = linear & 31;               // 0..31
            float4 w4 = *(const float4*)(Wt + (k0 + k) * CK + m0 + q32 * 4);
            float2* ad = (float2*)&Asd[k][q32 * 8];
            ad[0] = make_float2(w4.x, w4.x);
            ad[1] = make_float2(w4.y, w4.y);
            ad[2] = make_float2(w4.z, w4.z);
            ad[3] = make_float2(w4.w, w4.w);
            float4 x4 = *(const float4*)(X + (size_t)(k0 + k) * HW + n0 + q32 * 4);
            *(float4*)&Bs[k][q32 * 4] = x4;
        }
        __syncthreads();

        // ---- compute ----
#pragma unroll
        for (int k = 0; k < 16; k++) {
            const unsigned long long* aup = (const unsigned long long*)&Asd[k][0];
            const unsigned long long* bup = (const unsigned long long*)&Bs[k][0];
            unsigned long long ad[8], bp[4];
#pragma unroll
            for (int i = 0; i < 4; i++) {
                ad[i]     = aup[tm * 4 + i];        // rows tm*4 .. tm*4+3 (dup pairs)
                ad[4 + i] = aup[64 + tm * 4 + i];   // rows 64+tm*4 ..
            }
#pragma unroll
            for (int q = 0; q < 2; q++) {
                bp[q]     = bup[tn * 2 + q];        // cols 4tn+2q, 4tn+2q+1
                bp[2 + q] = bup[32 + tn * 2 + q];   // cols 64+4tn+2q, ...
            }
#pragma unroll
            for (int i = 0; i < 8; i++)
#pragma unroll
                for (int q = 0; q < 4; q++) ffma2(acc[i][q], ad[i], bp[q]);
        }
        __syncthreads();
    }

    // ---- epilogue ----
    float* Fp = g_F + (size_t)blockIdx.z * CK * HW;
#pragma unroll
    for (int i = 0; i < 8; i++) {
        int row = m0 + ((i < 4) ? (tm * 4 + i) : (64 + tm * 4 + i - 4));
        float2 p0 = unpk(acc[i][0]), p1 = unpk(acc[i][1]);
        *(float4*)(Fp + (size_t)row * HW + n0 + tn * 4) =
            make_float4(p0.x, p0.y, p1.x, p1.y);
        float2 p2 = unpk(acc[i][2]), p3 = unpk(acc[i][3]);
        *(float4*)(Fp + (size_t)row * HW + n0 + 64 + tn * 4) =
            make_float4(p2.x, p2.y, p3.x, p3.y);
    }
}

// ============================================================
// K2: S[b,c] = F^T F per (br,b,c). One block per (br*4096 + b*512 + c).
// ============================================================
__global__ __launch_bounds__(256) void k2_gram() {
    __shared__ float Fs[4096];      // F[h][w], 64x64
    size_t base = (size_t)blockIdx.x * HW;
    const float4* Fp = (const float4*)(g_F + base);
    for (int t = threadIdx.x; t < 1024; t += 256) ((float4*)Fs)[t] = Fp[t];
    __syncthreads();

    int ti = threadIdx.x >> 4, tj = threadIdx.x & 15;
    float acc[4][4] = {};
    for (int h = 0; h < 64; h++) {
        float4 a  = *(const float4*)&Fs[h * 64 + ti * 4];
        float4 bb = *(const float4*)&Fs[h * 64 + tj * 4];
        float av[4] = {a.x, a.y, a.z, a.w};
        float bv[4] = {bb.x, bb.y, bb.z, bb.w};
#pragma unroll
        for (int di = 0; di < 4; di++)
#pragma unroll
            for (int dj = 0; dj < 4; dj++) acc[di][dj] += av[di] * bv[dj];
    }
    float* Sp = g_S + base;
#pragma unroll
    for (int di = 0; di < 4; di++)
        *(float4*)&Sp[(ti * 4 + di) * 64 + tj * 4] =
            make_float4(acc[di][0], acc[di][1], acc[di][2], acc[di][3]);
}

// ============================================================
// K3: online softmax stats over channel dim c (512) per (br,b,i,j)
//     grid (16 i-groups, 8 b, 2 br); thread -> (i = bx*4 + t/64, j = t%64)
// ============================================================
__global__ __launch_bounds__(256) void k3_stats() {
    int j  = threadIdx.x & 63;
    int i  = blockIdx.x * 4 + (threadIdx.x >> 6);
    int bb = blockIdx.y, br = blockIdx.z;
    const float* Sp = g_S + ((size_t)(br * 8 + bb) * CK) * HW + i * 64 + j;

    float m = -3.0e38f, s = 0.f;
#pragma unroll 4
    for (int c = 0; c < 512; c++) {
        float v  = Sp[(size_t)c * HW];
        float nm = fmaxf(m, v);
        s = s * __expf(m - nm) + __expf(v - nm);
        m = nm;
    }
    int si = (br * 8 + bb) * HW + i * 64 + j;
    g_mx[si] = m;
    g_sm[si] = s;
}

// ============================================================
// K4: Att = f0*f1*exp(2*(S0-m0 + S1-m1)) / (Z0*Z1)^2   (one exp/elem)
//     One block per (b,c) row of 4096 elements.
// ============================================================
__global__ __launch_bounds__(256) void k4_final(float* __restrict__ out) {
    int bc = blockIdx.x;            // b*512 + c
    int bb = bc >> 9;
    size_t off0 = (size_t)bc * HW;
    size_t off1 = off0 + (size_t)BB * CK * HW;
    const float4* F0 = (const float4*)(g_F + off0);
    const float4* F1 = (const float4*)(g_F + off1);
    const float4* S0 = (const float4*)(g_S + off0);
    const float4* S1 = (const float4*)(g_S + off1);
    const float4* M0 = (const float4*)(g_mx + bb * HW);
    const float4* M1 = (const float4*)(g_mx + (8 + bb) * HW);
    const float4* Z0 = (const float4*)(g_sm + bb * HW);
    const float4* Z1 = (const float4*)(g_sm + (8 + bb) * HW);
    float4* O = (float4*)(out + off0);

    for (int p = threadIdx.x; p < 1024; p += 256) {
        float4 f0 = F0[p], f1 = F1[p], s0 = S0[p], s1 = S1[p];
        float4 m0 = M0[p], m1 = M1[p], z0 = Z0[p], z1 = Z1[p];
        float4 o;
        {
            float e = __expf(2.f * ((s0.x - m0.x) + (s1.x - m1.x)));
            float inv = 1.f / (z0.x * z1.x);
            o.x = f0.x * f1.x * e * inv * inv;
        }
        {
            float e = __expf(2.f * ((s0.y - m0.y) + (s1.y - m1.y)));
            float inv = 1.f / (z0.y * z1.y);
            o.y = f0.y * f1.y * e * inv * inv;
        }
        {
            float e = __expf(2.f * ((s0.z - m0.z) + (s1.z - m1.z)));
            float inv = 1.f / (z0.z * z1.z);
            o.z = f0.z * f1.z * e * inv * inv;
        }
        {
            float e = __expf(2.f * ((s0.w - m0.w) + (s1.w - m1.w)));
            float inv = 1.f / (z0.w * z1.w);
            o.w = f0.w * f1.w * e * inv * inv;
        }
        O[p] = o;
    }
}

// ============================================================
extern "C" void kernel_launch(void* const* d_in, const int* in_sizes, int n_in,
                              void* d_out, int out_size) {
    const float* opt = (const float*)d_in[0];
    const float* sar = (const float*)d_in[1];
    const float* Wo  = (const float*)d_in[2];
    const float* Ws  = (const float*)d_in[3];

    k0_transpose<<<2048, 256>>>(Wo, Ws);
    k1_gemm<<<dim3(32, 4, 16), 256>>>(opt, sar);
    k2_gram<<<2 * BB * CK, 256>>>();
    k3_stats<<<dim3(16, 8, 2), 256>>>();
    k4_final<<<BB * CK, 256>>>((float*)d_out);
}

// round 7
// speedup vs baseline: 1.1973x; 1.1973x over previous
#include <cuda_runtime.h>
#include <cstdint>
#include <cstddef>

// Problem constants: B=8, C=512, H=W=64
#define CK 512
#define BB 8
#define HW 4096   // 64*64

// ---------------- scratch (device globals; allocation-free rule) ----------------
__device__ __align__(16) float g_F[2ull * BB * CK * HW];   // f per branch (134 MB)
__device__ __align__(16) float g_S[2ull * BB * CK * HW];   // S per branch (134 MB)
__device__ float g_mx[2 * BB * HW];
__device__ float g_sm[2 * BB * HW];

// ---------------- helpers ----------------
__device__ __forceinline__ uint32_t smem_u32(const void* p) {
    uint32_t a;
    asm("{ .reg .u64 t; cvta.to.shared.u64 t, %1; cvt.u32.u64 %0, t; }" : "=r"(a) : "l"(p));
    return a;
}
// tf32 2-limb split: hi = rna(x), lo = rna(x - hi). Both valid tf32 operands.
__device__ __forceinline__ void split_tf32(float x, uint32_t& hi, uint32_t& lo) {
    asm("cvt.rna.tf32.f32 %0, %1;" : "=r"(hi) : "f"(x));
    float lf = __fsub_rn(x, __uint_as_float(hi));
    asm("cvt.rna.tf32.f32 %0, %1;" : "=r"(lo) : "f"(lf));
}
__device__ __forceinline__ void mma_tf32(float* c, const uint32_t* a, const uint32_t* b) {
    asm volatile(
        "mma.sync.aligned.m16n8k8.row.col.f32.tf32.tf32.f32 "
        "{%0,%1,%2,%3}, {%4,%5,%6,%7}, {%8,%9}, {%0,%1,%2,%3};"
        : "+f"(c[0]), "+f"(c[1]), "+f"(c[2]), "+f"(c[3])
        : "r"(a[0]), "r"(a[1]), "r"(a[2]), "r"(a[3]), "r"(b[0]), "r"(b[1]));
}
__device__ __forceinline__ void ldsm_x4(uint32_t* r, uint32_t addr) {
    asm volatile("ldmatrix.sync.aligned.m8n8.x4.shared.b16 {%0,%1,%2,%3}, [%4];"
                 : "=r"(r[0]), "=r"(r[1]), "=r"(r[2]), "=r"(r[3]) : "r"(addr));
}
// packed fp32x2 FMA (FFMA2)
__device__ __forceinline__ void ffma2(unsigned long long& d, unsigned long long a,
                                      unsigned long long b) {
    asm("fma.rn.f32x2 %0, %1, %2, %3;" : "=l"(d) : "l"(a), "l"(b), "l"(d));
}
__device__ __forceinline__ unsigned long long pk2(float x, float y) {
    unsigned long long r;
    asm("mov.b64 %0, {%1, %2};" : "=l"(r) : "f"(x), "f"(y));
    return r;
}
__device__ __forceinline__ float2 unpk(unsigned long long v) {
    float2 r;
    asm("mov.b64 {%0, %1}, %2;" : "=f"(r.x), "=f"(r.y) : "l"(v));
    return r;
}

// ============================================================
// K1: f = W @ X via mma.sync tf32 (2-limb, 3 products, fp32 accum).
//     CTA tile 128(M=o) x 128(N=pix), k-chunk 16, double-buffered smem.
//     8 warps: warp tile 64x32 (wm = wid/4, wn = wid%4); mt=4, nt=4.
//     A smem: [m 0..127][k 0..15] pad 20 (ldmatrix, conflict-free).
//     B smem: [k 0..15][n 0..127] pad 136 (scalar LDS, conflict-free).
// ============================================================
#define APAD 20
#define BPAD 136
#define ABUF (128 * APAD)   // 2560 floats
#define BBUF (16 * BPAD)    // 2176 floats

__global__ __launch_bounds__(256) void k1_tc(const float* __restrict__ opt,
                                             const float* __restrict__ sar,
                                             const float* __restrict__ Wo,
                                             const float* __restrict__ Ws) {
    __shared__ float sA[2][ABUF];
    __shared__ float sB[2][BBUF];

    int t = threadIdx.x, lane = t & 31, wid = t >> 5;
    int wm = wid >> 2, wn = wid & 3;          // 2 x 4 warp grid
    int bz = blockIdx.z, br = bz >> 3, b = bz & 7;
    const float* W = br ? Ws : Wo;
    const float* X = (br ? sar : opt) + (size_t)b * CK * HW;
    int m0 = blockIdx.y * 128, n0 = blockIdx.x * 128;

    // staging indices
    int am = t >> 1, ak = (t & 1) * 8;        // A: row am, k ak..ak+7
    int bk = t >> 4, bn = (t & 15) * 8;       // B: k-row bk, n bn..bn+7

    uint32_t sAu = smem_u32(&sA[0][0]);

    float acc[4][4][4];
#pragma unroll
    for (int i = 0; i < 4; i++)
#pragma unroll
        for (int j = 0; j < 4; j++)
#pragma unroll
            for (int q = 0; q < 4; q++) acc[i][j][q] = 0.f;

    // prologue: stage chunk 0 into buffer 0
    {
        float4 a0 = *(const float4*)(W + (m0 + am) * CK + ak);
        float4 a1 = *(const float4*)(W + (m0 + am) * CK + ak + 4);
        float4 b0 = *(const float4*)(X + (size_t)bk * HW + n0 + bn);
        float4 b1 = *(const float4*)(X + (size_t)bk * HW + n0 + bn + 4);
        *(float4*)&sA[0][am * APAD + ak]     = a0;
        *(float4*)&sA[0][am * APAD + ak + 4] = a1;
        *(float4*)&sB[0][bk * BPAD + bn]     = b0;
        *(float4*)&sB[0][bk * BPAD + bn + 4] = b1;
    }

    int g8 = lane >> 3, r8 = lane & 7;        // ldmatrix lane decomposition
    int tg = lane & 3, gq = lane >> 2;        // mma fragment lane decomposition

    for (int ch = 0; ch < 32; ch++) {
        __syncthreads();
        int cur = ch & 1;

        // early global loads for next chunk
        float4 na0, na1, nb0, nb1;
        if (ch < 31) {
            int kg = (ch + 1) * 16;
            na0 = *(const float4*)(W + (m0 + am) * CK + kg + ak);
            na1 = *(const float4*)(W + (m0 + am) * CK + kg + ak + 4);
            nb0 = *(const float4*)(X + (size_t)(kg + bk) * HW + n0 + bn);
            nb1 = *(const float4*)(X + (size_t)(kg + bk) * HW + n0 + bn + 4);
        }

        // ---- compute: 2 k8 steps ----
#pragma unroll
        for (int ks = 0; ks < 2; ks++) {
            // B fragments: raw fp32 from [k][n] smem, split to hi/lo
            uint32_t bh[4][2], bl[4][2];
#pragma unroll
            for (int nt = 0; nt < 4; nt++) {
                int nb2 = wn * 32 + nt * 8 + gq;
                float r0 = sB[cur][(ks * 8 + tg) * BPAD + nb2];
                float r1 = sB[cur][(ks * 8 + tg + 4) * BPAD + nb2];
                split_tf32(r0, bh[nt][0], bl[nt][0]);
                split_tf32(r1, bh[nt][1], bl[nt][1]);
            }
            // A fragments per m-tile via ldmatrix, split, 3-product mma
#pragma unroll
            for (int mt = 0; mt < 4; mt++) {
                int row = wm * 64 + mt * 16 + (g8 & 1) * 8 + r8;
                uint32_t addr = sAu + (uint32_t)cur * (ABUF * 4) +
                                (uint32_t)(row * APAD + ks * 8 + (g8 >> 1) * 4) * 4;
                uint32_t ar[4], ah[4], al[4];
                ldsm_x4(ar, addr);
#pragma unroll
                for (int q = 0; q < 4; q++)
                    split_tf32(__uint_as_float(ar[q]), ah[q], al[q]);
#pragma unroll
                for (int nt = 0; nt < 4; nt++) {
                    mma_tf32(acc[mt][nt], ah, bh[nt]);
                    mma_tf32(acc[mt][nt], ah, bl[nt]);
                    mma_tf32(acc[mt][nt], al, bh[nt]);
                }
            }
        }

        // store next chunk into other buffer
        if (ch < 31) {
            int nxt = cur ^ 1;
            *(float4*)&sA[nxt][am * APAD + ak]     = na0;
            *(float4*)&sA[nxt][am * APAD + ak + 4] = na1;
            *(float4*)&sB[nxt][bk * BPAD + bn]     = nb0;
            *(float4*)&sB[nxt][bk * BPAD + bn + 4] = nb1;
        }
    }

    // ---- epilogue: fragment -> gmem (float2 per c-pair) ----
    float* Fp = g_F + (size_t)bz * CK * HW;
#pragma unroll
    for (int mt = 0; mt < 4; mt++) {
#pragma unroll
        for (int nt = 0; nt < 4; nt++) {
            int row = m0 + wm * 64 + mt * 16 + gq;
            int col = n0 + wn * 32 + nt * 8 + 2 * tg;
            *(float2*)(Fp + (size_t)row * HW + col) =
                make_float2(acc[mt][nt][0], acc[mt][nt][1]);
            *(float2*)(Fp + (size_t)(row + 8) * HW + col) =
                make_float2(acc[mt][nt][2], acc[mt][nt][3]);
        }
    }
}

// ============================================================
// K2: S[b,c] = F^T F per (br,b,c), FFMA2 inner product. One block per bc.
// ============================================================
__global__ __launch_bounds__(256) void k2_gram() {
    __shared__ float Fs[4096];
    size_t base = (size_t)blockIdx.x * HW;
    const float4* Fp = (const float4*)(g_F + base);
    for (int t = threadIdx.x; t < 1024; t += 256) ((float4*)Fs)[t] = Fp[t];
    __syncthreads();

    int ti = threadIdx.x >> 4, tj = threadIdx.x & 15;
    unsigned long long accP[4][2];
#pragma unroll
    for (int di = 0; di < 4; di++) { accP[di][0] = 0ull; accP[di][1] = 0ull; }

    for (int h = 0; h < 64; h++) {
        float4 a  = *(const float4*)&Fs[h * 64 + ti * 4];
        float4 bb = *(const float4*)&Fs[h * 64 + tj * 4];
        unsigned long long b01 = pk2(bb.x, bb.y), b23 = pk2(bb.z, bb.w);
        float av[4] = {a.x, a.y, a.z, a.w};
#pragma unroll
        for (int di = 0; di < 4; di++) {
            unsigned long long au = pk2(av[di], av[di]);
            ffma2(accP[di][0], au, b01);
            ffma2(accP[di][1], au, b23);
        }
    }
    float* Sp = g_S + base;
#pragma unroll
    for (int di = 0; di < 4; di++) {
        float2 p0 = unpk(accP[di][0]), p1 = unpk(accP[di][1]);
        *(float4*)&Sp[(ti * 4 + di) * 64 + tj * 4] = make_float4(p0.x, p0.y, p1.x, p1.y);
    }
}

// ============================================================
// K3: channel-softmax stats, 4 independent online chains (MLP=4)
// ============================================================
__global__ __launch_bounds__(256) void k3_stats() {
    int j  = threadIdx.x & 63;
    int i  = blockIdx.x * 4 + (threadIdx.x >> 6);
    int bb = blockIdx.y, br = blockIdx.z;
    const float* Sp = g_S + ((size_t)(br * 8 + bb) * CK) * HW + i * 64 + j;

    float m[4] = {-3.0e38f, -3.0e38f, -3.0e38f, -3.0e38f};
    float s[4] = {0.f, 0.f, 0.f, 0.f};
    for (int c = 0; c < 512; c += 4) {
        float v[4];
#pragma unroll
        for (int q = 0; q < 4; q++) v[q] = Sp[(size_t)(c + q) * HW];
#pragma unroll
        for (int q = 0; q < 4; q++) {
            float nm = fmaxf(m[q], v[q]);
            s[q] = s[q] * __expf(m[q] - nm) + __expf(v[q] - nm);
            m[q] = nm;
        }
    }
    float M01 = fmaxf(m[0], m[1]);
    float S01 = s[0] * __expf(m[0] - M01) + s[1] * __expf(m[1] - M01);
    float M23 = fmaxf(m[2], m[3]);
    float S23 = s[2] * __expf(m[2] - M23) + s[3] * __expf(m[3] - M23);
    float M = fmaxf(M01, M23);
    float S = S01 * __expf(M01 - M) + S23 * __expf(M23 - M);

    int si = (br * 8 + bb) * HW + i * 64 + j;
    g_mx[si] = M;
    g_sm[si] = S;
}

// ============================================================
// K4: Att = f0*f1*exp(2*(S0-m0 + S1-m1)) / (Z0*Z1)^2
// ============================================================
__global__ __launch_bounds__(256) void k4_final(float* __restrict__ out) {
    int bc = blockIdx.x;
    int bb = bc >> 9;
    size_t off0 = (size_t)bc * HW;
    size_t off1 = off0 + (size_t)BB * CK * HW;
    const float4* F0 = (const float4*)(g_F + off0);
    const float4* F1 = (const float4*)(g_F + off1);
    const float4* S0 = (const float4*)(g_S + off0);
    const float4* S1 = (const float4*)(g_S + off1);
    const float4* M0 = (const float4*)(g_mx + bb * HW);
    const float4* M1 = (const float4*)(g_mx + (8 + bb) * HW);
    const float4* Z0 = (const float4*)(g_sm + bb * HW);
    const float4* Z1 = (const float4*)(g_sm + (8 + bb) * HW);
    float4* O = (float4*)(out + off0);

    for (int p = threadIdx.x; p < 1024; p += 256) {
        float4 f0 = F0[p], f1 = F1[p], s0 = S0[p], s1 = S1[p];
        float4 m0 = M0[p], m1 = M1[p], z0 = Z0[p], z1 = Z1[p];
        float4 o;
        {
            float e = __expf(2.f * ((s0.x - m0.x) + (s1.x - m1.x)));
            float inv = 1.f / (z0.x * z1.x);
            o.x = f0.x * f1.x * e * inv * inv;
        }
        {
            float e = __expf(2.f * ((s0.y - m0.y) + (s1.y - m1.y)));
            float inv = 1.f / (z0.y * z1.y);
            o.y = f0.y * f1.y * e * inv * inv;
        }
        {
            float e = __expf(2.f * ((s0.z - m0.z) + (s1.z - m1.z)));
            float inv = 1.f / (z0.z * z1.z);
            o.z = f0.z * f1.z * e * inv * inv;
        }
        {
            float e = __expf(2.f * ((s0.w - m0.w) + (s1.w - m1.w)));
            float inv = 1.f / (z0.w * z1.w);
            o.w = f0.w * f1.w * e * inv * inv;
        }
        O[p] = o;
    }
}

// ============================================================
extern "C" void kernel_launch(void* const* d_in, const int* in_sizes, int n_in,
                              void* d_out, int out_size) {
    const float* opt = (const float*)d_in[0];
    const float* sar = (const float*)d_in[1];
    const float* Wo  = (const float*)d_in[2];
    const float* Ws  = (const float*)d_in[3];

    k1_tc<<<dim3(32, 4, 16), 256>>>(opt, sar, Wo, Ws);
    k2_gram<<<2 * BB * CK, 256>>>();
    k3_stats<<<dim3(16, 8, 2), 256>>>();
    k4_final<<<BB * CK, 256>>>((float*)d_out);
}

// round 8
// speedup vs baseline: 1.2464x; 1.0410x over previous
#include <cuda_runtime.h>
#include <cstdint>
#include <cstddef>

// Problem constants: B=8, C=512, H=W=64
#define CK 512
#define BB 8
#define HW 4096   // 64*64

// ---------------- scratch (device globals; allocation-free rule) ----------------
__device__ __align__(16) float g_F[2ull * BB * CK * HW];   // f per branch (134 MB)
__device__ __align__(16) float g_S[2ull * BB * CK * HW];   // S per branch (134 MB)
__device__ float g_mx[2 * BB * HW];
__device__ float g_sm[2 * BB * HW];

// ---------------- helpers ----------------
__device__ __forceinline__ uint32_t smem_u32(const void* p) {
    uint32_t a;
    asm("{ .reg .u64 t; cvta.to.shared.u64 t, %1; cvt.u32.u64 %0, t; }" : "=r"(a) : "l"(p));
    return a;
}
// tf32 2-limb split: hi = rna(x), lo = rna(x - hi). Both valid tf32 operands.
__device__ __forceinline__ void split_tf32_f(float x, float& hi, float& lo) {
    uint32_t h, l;
    asm("cvt.rna.tf32.f32 %0, %1;" : "=r"(h) : "f"(x));
    float lf = __fsub_rn(x, __uint_as_float(h));
    asm("cvt.rna.tf32.f32 %0, %1;" : "=r"(l) : "f"(lf));
    hi = __uint_as_float(h);
    lo = __uint_as_float(l);
}
__device__ __forceinline__ void mma_tf32(float* c, const uint32_t* a, const uint32_t* b) {
    asm volatile(
        "mma.sync.aligned.m16n8k8.row.col.f32.tf32.tf32.f32 "
        "{%0,%1,%2,%3}, {%4,%5,%6,%7}, {%8,%9}, {%0,%1,%2,%3};"
        : "+f"(c[0]), "+f"(c[1]), "+f"(c[2]), "+f"(c[3])
        : "r"(a[0]), "r"(a[1]), "r"(a[2]), "r"(a[3]), "r"(b[0]), "r"(b[1]));
}
__device__ __forceinline__ void ldsm_x4(uint32_t* r, uint32_t addr) {
    asm volatile("ldmatrix.sync.aligned.m8n8.x4.shared.b16 {%0,%1,%2,%3}, [%4];"
                 : "=r"(r[0]), "=r"(r[1]), "=r"(r[2]), "=r"(r[3]) : "r"(addr));
}
// packed fp32x2 FMA (FFMA2)
__device__ __forceinline__ void ffma2(unsigned long long& d, unsigned long long a,
                                      unsigned long long b) {
    asm("fma.rn.f32x2 %0, %1, %2, %3;" : "=l"(d) : "l"(a), "l"(b), "l"(d));
}
__device__ __forceinline__ unsigned long long pk2(float x, float y) {
    unsigned long long r;
    asm("mov.b64 %0, {%1, %2};" : "=l"(r) : "f"(x), "f"(y));
    return r;
}
__device__ __forceinline__ float2 unpk(unsigned long long v) {
    float2 r;
    asm("mov.b64 {%0, %1}, %2;" : "=f"(r.x), "=f"(r.y) : "l"(v));
    return r;
}

// ============================================================
// K1: f = W @ X via mma.sync tf32, 2-limb split PRE-SPLIT AT STAGING.
//     CTA tile 128(M=o) x 128(N=pix), k-chunk 16, double-buffered.
//     smem planes: sAH/sAL [2][128][APAD], sBH/sBL [2][16][BPAD].
//     8 warps: warp tile 64x32 (wm = wid>>2, wn = wid&3); mt=4, nt=4.
// ============================================================
#define APAD 20
#define BPAD 136
#define ABUF (128 * APAD)   // 2560 floats per buffer
#define BBUF (16 * BPAD)    // 2176 floats per buffer
#define SMEM_K1_BYTES ((4 * 2 * ABUF + 4 * 2 * BBUF) / 2 * 4)  // (2*ABUF*2 + 2*BBUF*2) floats * 4B
// = (2*2560*2 + 2*2176*2)*4 = 75776 bytes

__global__ __launch_bounds__(256, 2) void k1_tc(const float* __restrict__ opt,
                                                const float* __restrict__ sar,
                                                const float* __restrict__ Wo,
                                                const float* __restrict__ Ws) {
    extern __shared__ float smem[];
    float* sAH = smem;                     // [2][ABUF]
    float* sAL = smem + 2 * ABUF;          // [2][ABUF]
    float* sBH = smem + 4 * ABUF;          // [2][BBUF]
    float* sBL = smem + 4 * ABUF + 2 * BBUF;

    int t = threadIdx.x, lane = t & 31, wid = t >> 5;
    int wm = wid >> 2, wn = wid & 3;       // 2 x 4 warp grid
    int bz = blockIdx.z, br = bz >> 3, b = bz & 7;
    const float* W = br ? Ws : Wo;
    const float* X = (br ? sar : opt) + (size_t)b * CK * HW;
    int m0 = blockIdx.y * 128, n0 = blockIdx.x * 128;

    // staging indices
    int am = t >> 1, ak = (t & 1) * 8;     // A: row am, k ak..ak+7
    int bk = t >> 4, bn = (t & 15) * 8;    // B: k-row bk, n bn..bn+7

    uint32_t sAHu = smem_u32(sAH);
    uint32_t sALu = smem_u32(sAL);

    float acc[4][4][4];
#pragma unroll
    for (int i = 0; i < 4; i++)
#pragma unroll
        for (int j = 0; j < 4; j++)
#pragma unroll
            for (int q = 0; q < 4; q++) acc[i][j][q] = 0.f;

    // ---- stage one chunk (split at staging) ----
    auto stage = [&](int buf, float4 a0, float4 a1, float4 b0, float4 b1) {
        float4 h, l;
        split_tf32_f(a0.x, h.x, l.x); split_tf32_f(a0.y, h.y, l.y);
        split_tf32_f(a0.z, h.z, l.z); split_tf32_f(a0.w, h.w, l.w);
        *(float4*)&sAH[buf * ABUF + am * APAD + ak] = h;
        *(float4*)&sAL[buf * ABUF + am * APAD + ak] = l;
        split_tf32_f(a1.x, h.x, l.x); split_tf32_f(a1.y, h.y, l.y);
        split_tf32_f(a1.z, h.z, l.z); split_tf32_f(a1.w, h.w, l.w);
        *(float4*)&sAH[buf * ABUF + am * APAD + ak + 4] = h;
        *(float4*)&sAL[buf * ABUF + am * APAD + ak + 4] = l;
        split_tf32_f(b0.x, h.x, l.x); split_tf32_f(b0.y, h.y, l.y);
        split_tf32_f(b0.z, h.z, l.z); split_tf32_f(b0.w, h.w, l.w);
        *(float4*)&sBH[buf * BBUF + bk * BPAD + bn] = h;
        *(float4*)&sBL[buf * BBUF + bk * BPAD + bn] = l;
        split_tf32_f(b1.x, h.x, l.x); split_tf32_f(b1.y, h.y, l.y);
        split_tf32_f(b1.z, h.z, l.z); split_tf32_f(b1.w, h.w, l.w);
        *(float4*)&sBH[buf * BBUF + bk * BPAD + bn + 4] = h;
        *(float4*)&sBL[buf * BBUF + bk * BPAD + bn + 4] = l;
    };

    // prologue: chunk 0 -> buffer 0
    {
        float4 a0 = *(const float4*)(W + (m0 + am) * CK + ak);
        float4 a1 = *(const float4*)(W + (m0 + am) * CK + ak + 4);
        float4 b0 = *(const float4*)(X + (size_t)bk * HW + n0 + bn);
        float4 b1 = *(const float4*)(X + (size_t)bk * HW + n0 + bn + 4);
        stage(0, a0, a1, b0, b1);
    }

    int g8 = lane >> 3, r8 = lane & 7;     // ldmatrix lane decomposition
    int tg = lane & 3, gq = lane >> 2;     // mma fragment lane decomposition

    for (int ch = 0; ch < 32; ch++) {
        __syncthreads();
        int cur = ch & 1;

        // early global loads for next chunk
        float4 na0, na1, nb0, nb1;
        if (ch < 31) {
            int kg = (ch + 1) * 16;
            na0 = *(const float4*)(W + (m0 + am) * CK + kg + ak);
            na1 = *(const float4*)(W + (m0 + am) * CK + kg + ak + 4);
            nb0 = *(const float4*)(X + (size_t)(kg + bk) * HW + n0 + bn);
            nb1 = *(const float4*)(X + (size_t)(kg + bk) * HW + n0 + bn + 4);
        }

        // ---- compute: 2 k8 steps; operands already split in smem ----
#pragma unroll
        for (int ks = 0; ks < 2; ks++) {
            uint32_t bh[4][2], bl[4][2];
#pragma unroll
            for (int nt = 0; nt < 4; nt++) {
                int col = wn * 32 + nt * 8 + gq;
                int i0 = cur * BBUF + (ks * 8 + tg) * BPAD + col;
                int i1 = cur * BBUF + (ks * 8 + tg + 4) * BPAD + col;
                bh[nt][0] = __float_as_uint(sBH[i0]);
                bh[nt][1] = __float_as_uint(sBH[i1]);
                bl[nt][0] = __float_as_uint(sBL[i0]);
                bl[nt][1] = __float_as_uint(sBL[i1]);
            }
#pragma unroll
            for (int mt = 0; mt < 4; mt++) {
                int row = wm * 64 + mt * 16 + (g8 & 1) * 8 + r8;
                uint32_t off = (uint32_t)(cur * ABUF + row * APAD + ks * 8 + (g8 >> 1) * 4) * 4;
                uint32_t ah[4], al[4];
                ldsm_x4(ah, sAHu + off);
                ldsm_x4(al, sALu + off);
#pragma unroll
                for (int nt = 0; nt < 4; nt++) {
                    mma_tf32(acc[mt][nt], ah, bh[nt]);
                    mma_tf32(acc[mt][nt], ah, bl[nt]);
                    mma_tf32(acc[mt][nt], al, bh[nt]);
                }
            }
        }

        // split + store next chunk into other buffer
        if (ch < 31) stage(cur ^ 1, na0, na1, nb0, nb1);
    }

    // ---- epilogue: smem transpose -> coalesced STG.128 ----
    __syncthreads();
    float* sT = smem;                      // [128][132] = 16896 floats (fits 18944)
#pragma unroll
    for (int mt = 0; mt < 4; mt++) {
#pragma unroll
        for (int nt = 0; nt < 4; nt++) {
            int r1 = wm * 64 + mt * 16 + gq;
            int col = wn * 32 + nt * 8 + 2 * tg;
            sT[r1 * 132 + col]       = acc[mt][nt][0];
            sT[r1 * 132 + col + 1]   = acc[mt][nt][1];
            sT[(r1 + 8) * 132 + col]     = acc[mt][nt][2];
            sT[(r1 + 8) * 132 + col + 1] = acc[mt][nt][3];
        }
    }
    __syncthreads();
    {
        float* Fp = g_F + (size_t)bz * CK * HW;
        int row = t >> 1, cb = (t & 1) * 64;
        float* dst = Fp + (size_t)(m0 + row) * HW + n0 + cb;
        const float* src = &sT[row * 132 + cb];
#pragma unroll
        for (int e = 0; e < 16; e++) {
            *(float4*)(dst + e * 4) =
                make_float4(src[e * 4], src[e * 4 + 1], src[e * 4 + 2], src[e * 4 + 3]);
        }
    }
}

// ============================================================
// K2: S[b,c] = F^T F per (br,b,c), FFMA2 inner product. One block per bc.
// ============================================================
__global__ __launch_bounds__(256) void k2_gram() {
    __shared__ float Fs[4096];
    size_t base = (size_t)blockIdx.x * HW;
    const float4* Fp = (const float4*)(g_F + base);
    for (int t = threadIdx.x; t < 1024; t += 256) ((float4*)Fs)[t] = Fp[t];
    __syncthreads();

    int ti = threadIdx.x >> 4, tj = threadIdx.x & 15;
    unsigned long long accP[4][2];
#pragma unroll
    for (int di = 0; di < 4; di++) { accP[di][0] = 0ull; accP[di][1] = 0ull; }

    for (int h = 0; h < 64; h++) {
        float4 a  = *(const float4*)&Fs[h * 64 + ti * 4];
        float4 bb = *(const float4*)&Fs[h * 64 + tj * 4];
        unsigned long long b01 = pk2(bb.x, bb.y), b23 = pk2(bb.z, bb.w);
        float av[4] = {a.x, a.y, a.z, a.w};
#pragma unroll
        for (int di = 0; di < 4; di++) {
            unsigned long long au = pk2(av[di], av[di]);
            ffma2(accP[di][0], au, b01);
            ffma2(accP[di][1], au, b23);
        }
    }
    float* Sp = g_S + base;
#pragma unroll
    for (int di = 0; di < 4; di++) {
        float2 p0 = unpk(accP[di][0]), p1 = unpk(accP[di][1]);
        *(float4*)&Sp[(ti * 4 + di) * 64 + tj * 4] = make_float4(p0.x, p0.y, p1.x, p1.y);
    }
}

// ============================================================
// K3: channel-softmax stats, 4 independent online chains (MLP=4)
// ============================================================
__global__ __launch_bounds__(256) void k3_stats() {
    int j  = threadIdx.x & 63;
    int i  = blockIdx.x * 4 + (threadIdx.x >> 6);
    int bb = blockIdx.y, br = blockIdx.z;
    const float* Sp = g_S + ((size_t)(br * 8 + bb) * CK) * HW + i * 64 + j;

    float m[4] = {-3.0e38f, -3.0e38f, -3.0e38f, -3.0e38f};
    float s[4] = {0.f, 0.f, 0.f, 0.f};
    for (int c = 0; c < 512; c += 4) {
        float v[4];
#pragma unroll
        for (int q = 0; q < 4; q++) v[q] = Sp[(size_t)(c + q) * HW];
#pragma unroll
        for (int q = 0; q < 4; q++) {
            float nm = fmaxf(m[q], v[q]);
            s[q] = s[q] * __expf(m[q] - nm) + __expf(v[q] - nm);
            m[q] = nm;
        }
    }
    float M01 = fmaxf(m[0], m[1]);
    float S01 = s[0] * __expf(m[0] - M01) + s[1] * __expf(m[1] - M01);
    float M23 = fmaxf(m[2], m[3]);
    float S23 = s[2] * __expf(m[2] - M23) + s[3] * __expf(m[3] - M23);
    float M = fmaxf(M01, M23);
    float S = S01 * __expf(M01 - M) + S23 * __expf(M23 - M);

    int si = (br * 8 + bb) * HW + i * 64 + j;
    g_mx[si] = M;
    g_sm[si] = S;
}

// ============================================================
// K4: Att = f0*f1*exp(2*(S0-m0 + S1-m1)) / (Z0*Z1)^2
// ============================================================
__global__ __launch_bounds__(256) void k4_final(float* __restrict__ out) {
    int bc = blockIdx.x;
    int bb = bc >> 9;
    size_t off0 = (size_t)bc * HW;
    size_t off1 = off0 + (size_t)BB * CK * HW;
    const float4* F0 = (const float4*)(g_F + off0);
    const float4* F1 = (const float4*)(g_F + off1);
    const float4* S0 = (const float4*)(g_S + off0);
    const float4* S1 = (const float4*)(g_S + off1);
    const float4* M0 = (const float4*)(g_mx + bb * HW);
    const float4* M1 = (const float4*)(g_mx + (8 + bb) * HW);
    const float4* Z0 = (const float4*)(g_sm + bb * HW);
    const float4* Z1 = (const float4*)(g_sm + (8 + bb) * HW);
    float4* O = (float4*)(out + off0);

    for (int p = threadIdx.x; p < 1024; p += 256) {
        float4 f0 = F0[p], f1 = F1[p], s0 = S0[p], s1 = S1[p];
        float4 m0 = M0[p], m1 = M1[p], z0 = Z0[p], z1 = Z1[p];
        float4 o;
        {
            float e = __expf(2.f * ((s0.x - m0.x) + (s1.x - m1.x)));
            float inv = 1.f / (z0.x * z1.x);
            o.x = f0.x * f1.x * e * inv * inv;
        }
        {
            float e = __expf(2.f * ((s0.y - m0.y) + (s1.y - m1.y)));
            float inv = 1.f / (z0.y * z1.y);
            o.y = f0.y * f1.y * e * inv * inv;
        }
        {
            float e = __expf(2.f * ((s0.z - m0.z) + (s1.z - m1.z)));
            float inv = 1.f / (z0.z * z1.z);
            o.z = f0.z * f1.z * e * inv * inv;
        }
        {
            float e = __expf(2.f * ((s0.w - m0.w) + (s1.w - m1.w)));
            float inv = 1.f / (z0.w * z1.w);
            o.w = f0.w * f1.w * e * inv * inv;
        }
        O[p] = o;
    }
}

// ============================================================
extern "C" void kernel_launch(void* const* d_in, const int* in_sizes, int n_in,
                              void* d_out, int out_size) {
    const float* opt = (const float*)d_in[0];
    const float* sar = (const float*)d_in[1];
    const float* Wo  = (const float*)d_in[2];
    const float* Ws  = (const float*)d_in[3];

    static int smem_set = 0;
    if (!smem_set) {
        cudaFuncSetAttribute(k1_tc, cudaFuncAttributeMaxDynamicSharedMemorySize, 75776);
        smem_set = 1;
    }

    k1_tc<<<dim3(32, 4, 16), 256, 75776>>>(opt, sar, Wo, Ws);
    k2_gram<<<2 * BB * CK, 256>>>();
    k3_stats<<<dim3(16, 8, 2), 256>>>();
    k4_final<<<BB * CK, 256>>>((float*)d_out);
}

// round 10
// speedup vs baseline: 1.4361x; 1.1522x over previous
#include <cuda_runtime.h>
#include <cstdint>
#include <cstddef>

// Problem constants: B=8, C=512, H=W=64
#define CK 512
#define BB 8
#define HW 4096   // 64*64

// ---------------- scratch (device globals; allocation-free rule) ----------------
__device__ __align__(16) float g_F[2ull * BB * CK * HW];
__device__ __align__(16) float g_S[2ull * BB * CK * HW];
__device__ float g_mx[2 * BB * HW];
__device__ float g_sm[2 * BB * HW];

// ---------------- helpers ----------------
__device__ __forceinline__ uint32_t smem_u32(const void* p) {
    uint32_t a;
    asm("{ .reg .u64 t; cvta.to.shared.u64 t, %1; cvt.u32.u64 %0, t; }" : "=r"(a) : "l"(p));
    return a;
}
// tf32 2-limb split: hi = rna(x), lo = rna(x - hi).
__device__ __forceinline__ void split_tf32_f(float x, float& hi, float& lo) {
    uint32_t h, l;
    asm("cvt.rna.tf32.f32 %0, %1;" : "=r"(h) : "f"(x));
    float lf = __fsub_rn(x, __uint_as_float(h));
    asm("cvt.rna.tf32.f32 %0, %1;" : "=r"(l) : "f"(lf));
    hi = __uint_as_float(h);
    lo = __uint_as_float(l);
}
// pack two floats to bf16x2 (lo in low half)
__device__ __forceinline__ uint32_t bfpack(float lo, float hi) {
    uint32_t d;
    asm("cvt.rn.bf16x2.f32 %0, %1, %2;" : "=r"(d) : "f"(hi), "f"(lo));
    return d;
}
__device__ __forceinline__ void mma_tf32(float* c, const uint32_t* a, const uint32_t* b) {
    asm volatile(
        "mma.sync.aligned.m16n8k8.row.col.f32.tf32.tf32.f32 "
        "{%0,%1,%2,%3}, {%4,%5,%6,%7}, {%8,%9}, {%0,%1,%2,%3};"
        : "+f"(c[0]), "+f"(c[1]), "+f"(c[2]), "+f"(c[3])
        : "r"(a[0]), "r"(a[1]), "r"(a[2]), "r"(a[3]), "r"(b[0]), "r"(b[1]));
}
__device__ __forceinline__ void mma_bf16(float* c, const uint32_t* a, const uint32_t* b) {
    asm volatile(
        "mma.sync.aligned.m16n8k16.row.col.f32.bf16.bf16.f32 "
        "{%0,%1,%2,%3}, {%4,%5,%6,%7}, {%8,%9}, {%0,%1,%2,%3};"
        : "+f"(c[0]), "+f"(c[1]), "+f"(c[2]), "+f"(c[3])
        : "r"(a[0]), "r"(a[1]), "r"(a[2]), "r"(a[3]), "r"(b[0]), "r"(b[1]));
}
__device__ __forceinline__ void ldsm_x4(uint32_t* r, uint32_t addr) {
    asm volatile("ldmatrix.sync.aligned.m8n8.x4.shared.b16 {%0,%1,%2,%3}, [%4];"
                 : "=r"(r[0]), "=r"(r[1]), "=r"(r[2]), "=r"(r[3]) : "r"(addr));
}
__device__ __forceinline__ void ldsm_x2t(uint32_t* r, uint32_t addr) {
    asm volatile("ldmatrix.sync.aligned.m8n8.x2.trans.shared.b16 {%0,%1}, [%2];"
                 : "=r"(r[0]), "=r"(r[1]) : "r"(addr));
}
// packed fp32x2 FMA (FFMA2)
__device__ __forceinline__ void ffma2(unsigned long long& d, unsigned long long a,
                                      unsigned long long b) {
    asm("fma.rn.f32x2 %0, %1, %2, %3;" : "=l"(d) : "l"(a), "l"(b), "l"(d));
}
__device__ __forceinline__ unsigned long long pk2(float x, float y) {
    unsigned long long r;
    asm("mov.b64 %0, {%1, %2};" : "=l"(r) : "f"(x), "f"(y));
    return r;
}
__device__ __forceinline__ float2 unpk(unsigned long long v) {
    float2 r;
    asm("mov.b64 {%0, %1}, %2;" : "=f"(r.x), "=f"(r.y) : "l"(v));
    return r;
}

// ============================================================
// K1 smem layout (byte offsets), double-buffered per plane:
//   AH : tf32-hi as fp32, [128][20]  (pitch 80B)   10240 B/buf
//   AHB: bf16(a),         [128][24]  (pitch 48B)    6144 B/buf
//   ALB: bf16(al),        [128][24]  (pitch 48B)    6144 B/buf
//   BH : tf32-hi as fp32, [16][136]  (pitch 544B)   8704 B/buf
//   BHB: bf16(b),         [16][136]  (pitch 272B)   4352 B/buf
//   BLB: bf16(bl),        [16][136]  (pitch 272B)   4352 B/buf
// ============================================================
#define AH_OFF(b)  ((b) * 10240)
#define AHB_OFF(b) (20480 + (b) * 6144)
#define ALB_OFF(b) (32768 + (b) * 6144)
#define BH_OFF(b)  (45056 + (b) * 8704)
#define BHB_OFF(b) (62464 + (b) * 4352)
#define BLB_OFF(b) (71168 + (b) * 4352)
#define SMEM_K1 79872

__global__ __launch_bounds__(256, 2) void k1_tc(const float* __restrict__ opt,
                                                const float* __restrict__ sar,
                                                const float* __restrict__ Wo,
                                                const float* __restrict__ Ws) {
    extern __shared__ char sm[];
    uint32_t smu = smem_u32(sm);

    int t = threadIdx.x, lane = t & 31, wid = t >> 5;
    int wm = wid >> 2, wn = wid & 3;       // 2 x 4 warp grid, warp tile 64x32
    int bz = blockIdx.z, br = bz >> 3, b = bz & 7;
    const float* W = br ? Ws : Wo;
    const float* X = (br ? sar : opt) + (size_t)b * CK * HW;
    int m0 = blockIdx.y * 128, n0 = blockIdx.x * 128;

    // staging indices
    int am = t >> 1, ak = (t & 1) * 8;     // A: row am, k ak..ak+7
    int bk = t >> 4, bn = (t & 15) * 8;    // B: k-row bk, n bn..bn+7

    float acc[4][4][4];
#pragma unroll
    for (int i = 0; i < 4; i++)
#pragma unroll
        for (int j = 0; j < 4; j++)
#pragma unroll
            for (int q = 0; q < 4; q++) acc[i][j][q] = 0.f;

    // ---- stage one chunk: split into 6 planes ----
    auto stage = [&](int buf, float4 a0, float4 a1, float4 b0, float4 b1) {
        float av[8] = {a0.x, a0.y, a0.z, a0.w, a1.x, a1.y, a1.z, a1.w};
        float ah[8], al[8];
#pragma unroll
        for (int i = 0; i < 8; i++) split_tf32_f(av[i], ah[i], al[i]);
        *(float4*)(sm + AH_OFF(buf) + (am * 20 + ak) * 4) =
            make_float4(ah[0], ah[1], ah[2], ah[3]);
        *(float4*)(sm + AH_OFF(buf) + (am * 20 + ak + 4) * 4) =
            make_float4(ah[4], ah[5], ah[6], ah[7]);
        uint4 ph, pl;
        ph.x = bfpack(av[0], av[1]); ph.y = bfpack(av[2], av[3]);
        ph.z = bfpack(av[4], av[5]); ph.w = bfpack(av[6], av[7]);
        *(uint4*)(sm + AHB_OFF(buf) + am * 48 + ak * 2) = ph;
        pl.x = bfpack(al[0], al[1]); pl.y = bfpack(al[2], al[3]);
        pl.z = bfpack(al[4], al[5]); pl.w = bfpack(al[6], al[7]);
        *(uint4*)(sm + ALB_OFF(buf) + am * 48 + ak * 2) = pl;

        float bv[8] = {b0.x, b0.y, b0.z, b0.w, b1.x, b1.y, b1.z, b1.w};
        float bh[8], bl[8];
#pragma unroll
        for (int i = 0; i < 8; i++) split_tf32_f(bv[i], bh[i], bl[i]);
        *(float4*)(sm + BH_OFF(buf) + (bk * 136 + bn) * 4) =
            make_float4(bh[0], bh[1], bh[2], bh[3]);
        *(float4*)(sm + BH_OFF(buf) + (bk * 136 + bn + 4) * 4) =
            make_float4(bh[4], bh[5], bh[6], bh[7]);
        uint4 qh, ql;
        qh.x = bfpack(bv[0], bv[1]); qh.y = bfpack(bv[2], bv[3]);
        qh.z = bfpack(bv[4], bv[5]); qh.w = bfpack(bv[6], bv[7]);
        *(uint4*)(sm + BHB_OFF(buf) + bk * 272 + bn * 2) = qh;
        ql.x = bfpack(bl[0], bl[1]); ql.y = bfpack(bl[2], bl[3]);
        ql.z = bfpack(bl[4], bl[5]); ql.w = bfpack(bl[6], bl[7]);
        *(uint4*)(sm + BLB_OFF(buf) + bk * 272 + bn * 2) = ql;
    };

    // prologue: chunk 0 -> buffer 0
    {
        float4 a0 = *(const float4*)(W + (m0 + am) * CK + ak);
        float4 a1 = *(const float4*)(W + (m0 + am) * CK + ak + 4);
        float4 b0 = *(const float4*)(X + (size_t)bk * HW + n0 + bn);
        float4 b1 = *(const float4*)(X + (size_t)bk * HW + n0 + bn + 4);
        stage(0, a0, a1, b0, b1);
    }

    int g8 = lane >> 3, r8 = lane & 7;     // ldmatrix lane decomposition
    int tg = lane & 3, gq = lane >> 2;     // mma fragment lane decomposition
    int kr = lane & 15;                    // ldmatrix.x2.trans row lanes

    for (int ch = 0; ch < 32; ch++) {
        __syncthreads();
        int cur = ch & 1;

        // early global loads for next chunk
        float4 na0, na1, nb0, nb1;
        if (ch < 31) {
            int kg = (ch + 1) * 16;
            na0 = *(const float4*)(W + (m0 + am) * CK + kg + ak);
            na1 = *(const float4*)(W + (m0 + am) * CK + kg + ak + 4);
            nb0 = *(const float4*)(X + (size_t)(kg + bk) * HW + n0 + bn);
            nb1 = *(const float4*)(X + (size_t)(kg + bk) * HW + n0 + bn + 4);
        }

        // ---- P0: ah (x) bh in tf32, 2 k8 steps ----
#pragma unroll
        for (int ks = 0; ks < 2; ks++) {
            uint32_t bhf[4][2];
#pragma unroll
            for (int nt = 0; nt < 4; nt++) {
                int col = wn * 32 + nt * 8 + gq;
                bhf[nt][0] = *(const uint32_t*)(sm + BH_OFF(cur) +
                                                ((ks * 8 + tg) * 136 + col) * 4);
                bhf[nt][1] = *(const uint32_t*)(sm + BH_OFF(cur) +
                                                ((ks * 8 + tg + 4) * 136 + col) * 4);
            }
#pragma unroll
            for (int mt = 0; mt < 4; mt++) {
                int row = wm * 64 + mt * 16 + (g8 & 1) * 8 + r8;
                uint32_t a4[4];
                ldsm_x4(a4, smu + AH_OFF(cur) +
                            (uint32_t)(row * 80 + ks * 32 + (g8 >> 1) * 16));
#pragma unroll
                for (int nt = 0; nt < 4; nt++) mma_tf32(acc[mt][nt], a4, bhf[nt]);
            }
        }

        // ---- P1/P2: cross terms in bf16 m16n8k16 (1 step covers k16) ----
        {
            uint32_t bhb[4][2], blb[4][2];
#pragma unroll
            for (int nt = 0; nt < 4; nt++) {
                uint32_t cb = (uint32_t)(kr * 272 + (wn * 32 + nt * 8) * 2);
                ldsm_x2t(bhb[nt], smu + BHB_OFF(cur) + cb);
                ldsm_x2t(blb[nt], smu + BLB_OFF(cur) + cb);
            }
#pragma unroll
            for (int mt = 0; mt < 4; mt++) {
                int row = wm * 64 + mt * 16 + (g8 & 1) * 8 + r8;
                uint32_t koff = (uint32_t)(row * 48 + (g8 >> 1) * 16);
                uint32_t afl[4], afh[4];
                ldsm_x4(afl, smu + ALB_OFF(cur) + koff);
                ldsm_x4(afh, smu + AHB_OFF(cur) + koff);
#pragma unroll
                for (int nt = 0; nt < 4; nt++) mma_bf16(acc[mt][nt], afl, bhb[nt]);
#pragma unroll
                for (int nt = 0; nt < 4; nt++) mma_bf16(acc[mt][nt], afh, blb[nt]);
            }
        }

        // split + store next chunk into other buffer
        if (ch < 31) stage(cur ^ 1, na0, na1, nb0, nb1);
    }

    // ---- epilogue: smem transpose -> coalesced STG.128 ----
    __syncthreads();
    float* sT = (float*)sm;                // [128][132] = 67584 B (fits 79872)
#pragma unroll
    for (int mt = 0; mt < 4; mt++) {
#pragma unroll
        for (int nt = 0; nt < 4; nt++) {
            int r1 = wm * 64 + mt * 16 + gq;
            int col = wn * 32 + nt * 8 + 2 * tg;
            sT[r1 * 132 + col]           = acc[mt][nt][0];
            sT[r1 * 132 + col + 1]       = acc[mt][nt][1];
            sT[(r1 + 8) * 132 + col]     = acc[mt][nt][2];
            sT[(r1 + 8) * 132 + col + 1] = acc[mt][nt][3];
        }
    }
    __syncthreads();
    {
        float* Fp = g_F + (size_t)bz * CK * HW;
        int row = t >> 1, cb = (t & 1) * 64;
        float* dst = Fp + (size_t)(m0 + row) * HW + n0 + cb;
        const float* src = &sT[row * 132 + cb];
#pragma unroll
        for (int e = 0; e < 16; e++) {
            *(float4*)(dst + e * 4) =
                make_float4(src[e * 4], src[e * 4 + 1], src[e * 4 + 2], src[e * 4 + 3]);
        }
    }
}

// ============================================================
// K2: S[b,c] = F^T F per (br,b,c), FFMA2 inner product.
// ============================================================
__global__ __launch_bounds__(256) void k2_gram() {
    __shared__ float Fs[4096];
    size_t base = (size_t)blockIdx.x * HW;
    const float4* Fp = (const float4*)(g_F + base);
    for (int t = threadIdx.x; t < 1024; t += 256) ((float4*)Fs)[t] = Fp[t];
    __syncthreads();

    int ti = threadIdx.x >> 4, tj = threadIdx.x & 15;
    unsigned long long accP[4][2];
#pragma unroll
    for (int di = 0; di < 4; di++) { accP[di][0] = 0ull; accP[di][1] = 0ull; }

    for (int h = 0; h < 64; h++) {
        float4 a  = *(const float4*)&Fs[h * 64 + ti * 4];
        float4 bb = *(const float4*)&Fs[h * 64 + tj * 4];
        unsigned long long b01 = pk2(bb.x, bb.y), b23 = pk2(bb.z, bb.w);
        float av[4] = {a.x, a.y, a.z, a.w};
#pragma unroll
        for (int di = 0; di < 4; di++) {
            unsigned long long au = pk2(av[di], av[di]);
            ffma2(accP[di][0], au, b01);
            ffma2(accP[di][1], au, b23);
        }
    }
    float* Sp = g_S + base;
#pragma unroll
    for (int di = 0; di < 4; di++) {
        float2 p0 = unpk(accP[di][0]), p1 = unpk(accP[di][1]);
        *(float4*)&Sp[(ti * 4 + di) * 64 + tj * 4] = make_float4(p0.x, p0.y, p1.x, p1.y);
    }
}

// ============================================================
// K3: channel-softmax stats, 4 independent online chains
// ============================================================
__global__ __launch_bounds__(256) void k3_stats() {
    int j  = threadIdx.x & 63;
    int i  = blockIdx.x * 4 + (threadIdx.x >> 6);
    int bb = blockIdx.y, br = blockIdx.z;
    const float* Sp = g_S + ((size_t)(br * 8 + bb) * CK) * HW + i * 64 + j;

    float m[4] = {-3.0e38f, -3.0e38f, -3.0e38f, -3.0e38f};
    float s[4] = {0.f, 0.f, 0.f, 0.f};
    for (int c = 0; c < 512; c += 4) {
        float v[4];
#pragma unroll
        for (int q = 0; q < 4; q++) v[q] = Sp[(size_t)(c + q) * HW];
#pragma unroll
        for (int q = 0; q < 4; q++) {
            float nm = fmaxf(m[q], v[q]);
            s[q] = s[q] * __expf(m[q] - nm) + __expf(v[q] - nm);
            m[q] = nm;
        }
    }
    float M01 = fmaxf(m[0], m[1]);
    float S01 = s[0] * __expf(m[0] - M01) + s[1] * __expf(m[1] - M01);
    float M23 = fmaxf(m[2], m[3]);
    float S23 = s[2] * __expf(m[2] - M23) + s[3] * __expf(m[3] - M23);
    float M = fmaxf(M01, M23);
    float S = S01 * __expf(M01 - M) + S23 * __expf(M23 - M);

    int si = (br * 8 + bb) * HW + i * 64 + j;
    g_mx[si] = M;
    g_sm[si] = S;
}

// ============================================================
// K4: Att = f0*f1*exp(2*(S0-m0 + S1-m1)) / (Z0*Z1)^2
// ============================================================
__global__ __launch_bounds__(256) void k4_final(float* __restrict__ out) {
    int bc = blockIdx.x;
    int bb = bc >> 9;
    size_t off0 = (size_t)bc * HW;
    size_t off1 = off0 + (size_t)BB * CK * HW;
    const float4* F0 = (const float4*)(g_F + off0);
    const float4* F1 = (const float4*)(g_F + off1);
    const float4* S0 = (const float4*)(g_S + off0);
    const float4* S1 = (const float4*)(g_S + off1);
    const float4* M0 = (const float4*)(g_mx + bb * HW);
    const float4* M1 = (const float4*)(g_mx + (8 + bb) * HW);
    const float4* Z0 = (const float4*)(g_sm + bb * HW);
    const float4* Z1 = (const float4*)(g_sm + (8 + bb) * HW);
    float4* O = (float4*)(out + off0);

    for (int p = threadIdx.x; p < 1024; p += 256) {
        float4 f0 = F0[p], f1 = F1[p], s0 = S0[p], s1 = S1[p];
        float4 m0 = M0[p], m1 = M1[p], z0 = Z0[p], z1 = Z1[p];
        float4 o;
        {
            float e = __expf(2.f * ((s0.x - m0.x) + (s1.x - m1.x)));
            float inv = 1.f / (z0.x * z1.x);
            o.x = f0.x * f1.x * e * inv * inv;
        }
        {
            float e = __expf(2.f * ((s0.y - m0.y) + (s1.y - m1.y)));
            float inv = 1.f / (z0.y * z1.y);
            o.y = f0.y * f1.y * e * inv * inv;
        }
        {
            float e = __expf(2.f * ((s0.z - m0.z) + (s1.z - m1.z)));
            float inv = 1.f / (z0.z * z1.z);
            o.z = f0.z * f1.z * e * inv * inv;
        }
        {
            float e = __expf(2.f * ((s0.w - m0.w) + (s1.w - m1.w)));
            float inv = 1.f / (z0.w * z1.w);
            o.w = f0.w * f1.w * e * inv * inv;
        }
        O[p] = o;
    }
}

// ============================================================
extern "C" void kernel_launch(void* const* d_in, const int* in_sizes, int n_in,
                              void* d_out, int out_size) {
    const float* opt = (const float*)d_in[0];
    const float* sar = (const float*)d_in[1];
    const float* Wo  = (const float*)d_in[2];
    const float* Ws  = (const float*)d_in[3];

    static int smem_set = 0;
    if (!smem_set) {
        cudaFuncSetAttribute(k1_tc, cudaFuncAttributeMaxDynamicSharedMemorySize, SMEM_K1);
        smem_set = 1;
    }

    k1_tc<<<dim3(32, 4, 16), 256, SMEM_K1>>>(opt, sar, Wo, Ws);
    k2_gram<<<2 * BB * CK, 256>>>();
    k3_stats<<<dim3(16, 8, 2), 256>>>();
    k4_final<<<BB * CK, 256>>>((float*)d_out);
}